// round 6
// baseline (speedup 1.0000x reference)
#include <cuda_runtime.h>
#include <cstdint>
#include <math.h>

// Accurate libdevice log (what XLA emits for lax.log on f32): exact fallback
// paths so argmax ordering is provably identical to the reference.
extern "C" __device__ float __nv_logf(float);

// ---------------------------------------------------------------------------
// Compile-time Threefry-2x32 for split keys (partitionable fold-like split).
// ---------------------------------------------------------------------------
constexpr unsigned crotl(unsigned x, int r) { return (x << r) | (x >> (32 - r)); }
struct CKeys { unsigned a, b; };
constexpr CKeys ctf(unsigned k0, unsigned k1, unsigned x0, unsigned x1) {
    unsigned k2 = k0 ^ k1 ^ 0x1BD11BDAu;
    const int rotA[4] = {13, 15, 26, 6};
    const int rotB[4] = {17, 29, 16, 24};
    x0 += k0; x1 += k1;
    for (int i = 0; i < 4; i++) { x0 += x1; x1 = crotl(x1, rotA[i]); x1 ^= x0; }
    x0 += k1; x1 += k2 + 1u;
    for (int i = 0; i < 4; i++) { x0 += x1; x1 = crotl(x1, rotB[i]); x1 ^= x0; }
    x0 += k2; x1 += k0 + 2u;
    for (int i = 0; i < 4; i++) { x0 += x1; x1 = crotl(x1, rotA[i]); x1 ^= x0; }
    x0 += k0; x1 += k1 + 3u;
    for (int i = 0; i < 4; i++) { x0 += x1; x1 = crotl(x1, rotB[i]); x1 ^= x0; }
    x0 += k1; x1 += k2 + 4u;
    for (int i = 0; i < 4; i++) { x0 += x1; x1 = crotl(x1, rotA[i]); x1 ^= x0; }
    x0 += k2; x1 += k0 + 5u;
    return {x0, x1};
}
constexpr CKeys KCAT  = ctf(0u, 42u, 0u, 0u);   // k_cat
constexpr CKeys KBERN = ctf(0u, 42u, 0u, 1u);   // k_bern

// ---------------------------------------------------------------------------
// Device Threefry-2x32; partitionable 32-bit bits = lane0 ^ lane1, ctr (0, j).
// ---------------------------------------------------------------------------
__device__ __forceinline__ unsigned rotl(unsigned x, int r) {
    return __funnelshift_l(x, x, r);
}

__device__ __forceinline__ unsigned tf_bits32(unsigned k0, unsigned k1, unsigned x1) {
    unsigned k2 = k0 ^ k1 ^ 0x1BD11BDAu;
    unsigned x0 = k0;
    x1 += k1;
#define TFR(r) { x0 += x1; x1 = rotl(x1, r); x1 ^= x0; }
    TFR(13) TFR(15) TFR(26) TFR(6)
    x0 += k1; x1 += k2 + 1u;
    TFR(17) TFR(29) TFR(16) TFR(24)
    x0 += k2; x1 += k0 + 2u;
    TFR(13) TFR(15) TFR(26) TFR(6)
    x0 += k0; x1 += k1 + 3u;
    TFR(17) TFR(29) TFR(16) TFR(24)
    x0 += k1; x1 += k2 + 4u;
    TFR(13) TFR(15) TFR(26) TFR(6)
#undef TFR
    return (x0 + k2) ^ (x1 + k0 + 5u);
}

// JAX uniform [0,1): bitcast((bits>>9)|0x3f800000) - 1
__device__ __forceinline__ float u01f(unsigned bits) {
    return __uint_as_float((bits >> 9) | 0x3f800000u) - 1.0f;
}

#define TINY   1.17549435e-38f
#define T_MIN  0.001953125f   /* below this t, MUFU log(u) rel-err too big -> exact fix */
#define GAPTHR 1e-3f          /* >> max cheap-score error; proven in R5 */

// ---------------------------------------------------------------------------
// 4 windows per thread (single machine wave). Per row: batch all 8 threefry
// chains into g[8] (forces 8-way ILP), then the float phase. Cheap __logf
// scores with top-2 gap screen; rare exact-window fallback. Bernoulli via
// fast f32 sigmoid with double fallback in the 2e-3 boundary band.
// ---------------------------------------------------------------------------
__global__ __launch_bounds__(128)
void keypoint_sampler_kernel(const float* __restrict__ x, float* __restrict__ out) {
    const unsigned tid = blockIdx.x * 128u + threadIdx.x;   // 0 .. 131071

#pragma unroll 1
    for (int h = 0; h < 4; h++) {
        const unsigned w = tid + (unsigned)h * 131072u;     // 0 .. 524287

        const unsigned b  = w >> 16;
        const unsigned hc = (w >> 8) & 255u;
        const unsigned wc = w & 255u;

        const float* base = x + ((size_t)b << 22) + (size_t)(hc * 8u) * 2048u + wc * 8u;

        const unsigned bbits = tf_bits32(KBERN.a, KBERN.b, w);

        float best = -3.4e38f, b2 = -3.4e38f;
        int   bi   = 0;
        float esum = 0.0f;

        const unsigned cbase = w * 64u;

#pragma unroll 1
        for (int r = 0; r < 8; r++) {
            const float4 p0 = *(const float4*)(base + (size_t)r * 2048u);
            const float4 p1 = *(const float4*)(base + (size_t)r * 2048u + 4u);
            float v[8] = {p0.x, p0.y, p0.z, p0.w, p1.x, p1.y, p1.z, p1.w};

            const unsigned c = cbase + (unsigned)r * 8u;

            // Phase 1: 8 independent threefry chains live at once (ILP)
            unsigned g[8];
#pragma unroll
            for (int i = 0; i < 8; i++)
                g[i] = tf_bits32(KCAT.a, KCAT.b, c + (unsigned)i);

            // Phase 2: float math
#pragma unroll
            for (int i = 0; i < 8; i++) {
                const float u = fmaxf(u01f(g[i]), TINY);
                float t = -__logf(u);
                if (t < T_MIN) t = -__nv_logf(u);   // rare near-u=1 exact fix
                const float s = v[i] - __logf(t);
                esum += __expf(v[i]);
                if (s > best) { b2 = best; best = s; bi = r * 8 + i; }
                else          { b2 = fmaxf(b2, s); }
            }
        }

        // Ambiguous top-2 (P ~ 1e-3): redo window bitwise-exact.
        if (best - b2 < GAPTHR) {
            best = -3.4e38f; bi = 0;
#pragma unroll 1
            for (int r = 0; r < 8; r++) {
#pragma unroll 1
                for (int i = 0; i < 8; i++) {
                    const unsigned gb = tf_bits32(KCAT.a, KCAT.b,
                                                  cbase + (unsigned)(r * 8 + i));
                    const float uu = fmaxf(u01f(gb), TINY);
                    const float tt = -__nv_logf(uu);
                    const float s = __ldg(base + (size_t)r * 2048u + (unsigned)i)
                                    - __nv_logf(tt);
                    if (s > best) { best = s; bi = r * 8 + i; }
                }
            }
        }

        // Selected grid value via one cached load
        const float sel = __ldg(base + (size_t)(bi >> 3) * 2048u + (unsigned)(bi & 7));

        const float u = u01f(bbits);

        // Fast f32 sigmoid; double path only inside the 2e-3 boundary band.
        const float e    = __expf(-fabsf(sel));
        const float rr   = __fdividef(1.0f, 1.0f + e);
        const float sigf = (sel >= 0.0f) ? rr : 1.0f - rr;
        const float du   = u - sigf;
        bool acc;
        if (fabsf(du) > 2e-3f) {
            acc = du < 0.0f;
        } else {
            const double sig = 1.0 / (1.0 + exp(-(double)sel));
            acc = u < (float)sig;
        }

        const float lse     = log1pf(e);
        const float bern_lp = (acc ? fminf(sel, 0.0f) : fminf(-sel, 0.0f)) - lse;
        const float cat_lp  = sel - __logf(esum);   // abs err ~2e-6, tol 1e-3

        const int ddi = bi >> 3, ddj = bi & 7;

        // tuple layout: kp_xy [2*524288] | log_probs [524288] | mask [524288]
        ((float2*)out)[w]  = make_float2((float)(wc * 8u + (unsigned)ddj),   // x
                                         (float)(hc * 8u + (unsigned)ddi)); // y
        out[1048576u + w]  = cat_lp + bern_lp;
        out[1572864u + w]  = acc ? 1.0f : 0.0f;
    }
}

extern "C" void kernel_launch(void* const* d_in, const int* in_sizes, int n_in,
                              void* d_out, int out_size) {
    const float* x = (const float*)d_in[0];
    float* out = (float*)d_out;
    // 131072 threads, 4 windows each — single resident wave on 148 SMs
    keypoint_sampler_kernel<<<1024, 128>>>(x, out);
}

// round 7
// speedup vs baseline: 1.2570x; 1.2570x over previous
#include <cuda_runtime.h>
#include <cstdint>
#include <math.h>

// Accurate libdevice log (what XLA emits for lax.log on f32): exact fallback
// paths so argmax ordering is provably identical to the reference.
extern "C" __device__ float __nv_logf(float);

// ---------------------------------------------------------------------------
// Compile-time Threefry-2x32 for split keys (partitionable fold-like split).
// ---------------------------------------------------------------------------
constexpr unsigned crotl(unsigned x, int r) { return (x << r) | (x >> (32 - r)); }
struct CKeys { unsigned a, b; };
constexpr CKeys ctf(unsigned k0, unsigned k1, unsigned x0, unsigned x1) {
    unsigned k2 = k0 ^ k1 ^ 0x1BD11BDAu;
    const int rotA[4] = {13, 15, 26, 6};
    const int rotB[4] = {17, 29, 16, 24};
    x0 += k0; x1 += k1;
    for (int i = 0; i < 4; i++) { x0 += x1; x1 = crotl(x1, rotA[i]); x1 ^= x0; }
    x0 += k1; x1 += k2 + 1u;
    for (int i = 0; i < 4; i++) { x0 += x1; x1 = crotl(x1, rotB[i]); x1 ^= x0; }
    x0 += k2; x1 += k0 + 2u;
    for (int i = 0; i < 4; i++) { x0 += x1; x1 = crotl(x1, rotA[i]); x1 ^= x0; }
    x0 += k0; x1 += k1 + 3u;
    for (int i = 0; i < 4; i++) { x0 += x1; x1 = crotl(x1, rotB[i]); x1 ^= x0; }
    x0 += k1; x1 += k2 + 4u;
    for (int i = 0; i < 4; i++) { x0 += x1; x1 = crotl(x1, rotA[i]); x1 ^= x0; }
    x0 += k2; x1 += k0 + 5u;
    return {x0, x1};
}
constexpr CKeys KCAT  = ctf(0u, 42u, 0u, 0u);   // k_cat
constexpr CKeys KBERN = ctf(0u, 42u, 0u, 1u);   // k_bern

// ---------------------------------------------------------------------------
// Device Threefry-2x32; partitionable 32-bit bits = lane0 ^ lane1, ctr (0, j).
// ---------------------------------------------------------------------------
__device__ __forceinline__ unsigned rotl(unsigned x, int r) {
    return __funnelshift_l(x, x, r);
}

__device__ __forceinline__ unsigned tf_bits32(unsigned k0, unsigned k1, unsigned x1) {
    unsigned k2 = k0 ^ k1 ^ 0x1BD11BDAu;
    unsigned x0 = k0;
    x1 += k1;
#define TFR(r) { x0 += x1; x1 = rotl(x1, r); x1 ^= x0; }
    TFR(13) TFR(15) TFR(26) TFR(6)
    x0 += k1; x1 += k2 + 1u;
    TFR(17) TFR(29) TFR(16) TFR(24)
    x0 += k2; x1 += k0 + 2u;
    TFR(13) TFR(15) TFR(26) TFR(6)
    x0 += k0; x1 += k1 + 3u;
    TFR(17) TFR(29) TFR(16) TFR(24)
    x0 += k1; x1 += k2 + 4u;
    TFR(13) TFR(15) TFR(26) TFR(6)
#undef TFR
    return (x0 + k2) ^ (x1 + k0 + 5u);
}

// JAX uniform [0,1): bitcast((bits>>9)|0x3f800000) - 1
__device__ __forceinline__ float u01f(unsigned bits) {
    return __uint_as_float((bits >> 9) | 0x3f800000u) - 1.0f;
}

#define TINY   1.17549435e-38f
#define T_MIN  0.001953125f   /* below this t, MUFU log(u) rel-err too big -> exact fix */
#define GAPTHR 1e-3f          /* >> max cheap-score error (~2e-4); proven R5 */

// (value, index) max with exact second-max propagation; ties -> lower index
struct TopK { float v1; float v2; int i1; };
__device__ __forceinline__ TopK tk_merge(TopK a, TopK b) {
    TopK r;
    if (b.v1 > a.v1) { r.v1 = b.v1; r.i1 = b.i1; r.v2 = fmaxf(a.v1, b.v2); }
    else             { r.v1 = a.v1; r.i1 = a.i1; r.v2 = fmaxf(b.v1, a.v2); }
    return r;
}

// ---------------------------------------------------------------------------
// One thread per 8x8 window; ILP-restructured inner loop:
//   phase 1: 8 independent threefry chains -> g[8]
//   phase 2: 8 independent score computations, tournament top-2 (depth ~3),
//            4-way partial esum. Short dependency chains, MUFUs overlapped.
// ---------------------------------------------------------------------------
__global__ __launch_bounds__(128)
void keypoint_sampler_kernel(const float* __restrict__ x, float* __restrict__ out) {
    const unsigned w = blockIdx.x * 128u + threadIdx.x;   // 0 .. 524287

    const unsigned b  = w >> 16;
    const unsigned hc = (w >> 8) & 255u;
    const unsigned wc = w & 255u;

    const float* base = x + ((size_t)b << 22) + (size_t)(hc * 8u) * 2048u + wc * 8u;

    // Bernoulli bits early (independent ILP across the whole mainloop)
    const unsigned bbits = tf_bits32(KBERN.a, KBERN.b, w);

    TopK top; top.v1 = -3.4e38f; top.v2 = -3.4e38f; top.i1 = 0;
    float es0 = 0.f, es1 = 0.f, es2 = 0.f, es3 = 0.f;

    const unsigned cbase = w * 64u;

#pragma unroll 1
    for (int r = 0; r < 8; r++) {
        const float4 p0 = *(const float4*)(base + (size_t)r * 2048u);
        const float4 p1 = *(const float4*)(base + (size_t)r * 2048u + 4u);
        float v[8] = {p0.x, p0.y, p0.z, p0.w, p1.x, p1.y, p1.z, p1.w};

        const unsigned c = cbase + (unsigned)r * 8u;

        // Phase 1: 8 independent threefry chains in flight
        unsigned g[8];
#pragma unroll
        for (int i = 0; i < 8; i++)
            g[i] = tf_bits32(KCAT.a, KCAT.b, c + (unsigned)i);

        // Phase 2: 8 independent score pipelines (MUFU latency overlapped)
        float s[8];
#pragma unroll
        for (int i = 0; i < 8; i++) {
            const float u = fmaxf(u01f(g[i]), TINY);
            float t = -__logf(u);
            if (t < T_MIN) t = -__nv_logf(u);   // rare near-u=1 exact fix
            s[i] = v[i] - __logf(t);
        }
        es0 += __expf(v[0]) + __expf(v[4]);
        es1 += __expf(v[1]) + __expf(v[5]);
        es2 += __expf(v[2]) + __expf(v[6]);
        es3 += __expf(v[3]) + __expf(v[7]);

        // Tournament top-2 within the row (depth 3), ties -> lower index
        TopK t01, t23, t45, t67, ta, tb, row;
        t01.v1 = (s[1] > s[0]) ? s[1] : s[0];
        t01.i1 = (s[1] > s[0]) ? r*8+1 : r*8+0;
        t01.v2 = fminf(s[0], s[1]);
        t23.v1 = (s[3] > s[2]) ? s[3] : s[2];
        t23.i1 = (s[3] > s[2]) ? r*8+3 : r*8+2;
        t23.v2 = fminf(s[2], s[3]);
        t45.v1 = (s[5] > s[4]) ? s[5] : s[4];
        t45.i1 = (s[5] > s[4]) ? r*8+5 : r*8+4;
        t45.v2 = fminf(s[4], s[5]);
        t67.v1 = (s[7] > s[6]) ? s[7] : s[6];
        t67.i1 = (s[7] > s[6]) ? r*8+7 : r*8+6;
        t67.v2 = fminf(s[6], s[7]);
        ta  = tk_merge(t01, t23);
        tb  = tk_merge(t45, t67);
        row = tk_merge(ta, tb);
        top = tk_merge(top, row);
    }

    int bi = top.i1;

    // Ambiguous top-2 (P ~ 1e-3): redo window bitwise-exact.
    if (top.v1 - top.v2 < GAPTHR) {
        float best = -3.4e38f; bi = 0;
#pragma unroll 1
        for (int r = 0; r < 8; r++) {
#pragma unroll 1
            for (int i = 0; i < 8; i++) {
                const unsigned gb = tf_bits32(KCAT.a, KCAT.b,
                                              cbase + (unsigned)(r * 8 + i));
                const float uu = fmaxf(u01f(gb), TINY);
                const float tt = -__nv_logf(uu);
                const float s = __ldg(base + (size_t)r * 2048u + (unsigned)i)
                                - __nv_logf(tt);
                if (s > best) { best = s; bi = r * 8 + i; }
            }
        }
    }

    const float esum = (es0 + es1) + (es2 + es3);

    // Selected grid value via one cached load
    const float sel = __ldg(base + (size_t)(bi >> 3) * 2048u + (unsigned)(bi & 7));

    const float u = u01f(bbits);

    // Fast f32 sigmoid; double path only inside the 2e-3 boundary band.
    const float e    = __expf(-fabsf(sel));
    const float rr   = __fdividef(1.0f, 1.0f + e);
    const float sigf = (sel >= 0.0f) ? rr : 1.0f - rr;
    const float du   = u - sigf;
    bool acc;
    if (fabsf(du) > 2e-3f) {
        acc = du < 0.0f;
    } else {
        const double sig = 1.0 / (1.0 + exp(-(double)sel));
        acc = u < (float)sig;
    }

    const float lse     = log1pf(e);
    const float bern_lp = (acc ? fminf(sel, 0.0f) : fminf(-sel, 0.0f)) - lse;
    const float cat_lp  = sel - __logf(esum);   // abs err ~2e-6, tol 1e-3

    const int ddi = bi >> 3, ddj = bi & 7;

    // tuple layout: kp_xy [2*524288] | log_probs [524288] | mask [524288]
    ((float2*)out)[w]  = make_float2((float)(wc * 8u + (unsigned)ddj),   // x
                                     (float)(hc * 8u + (unsigned)ddi)); // y
    out[1048576u + w]  = cat_lp + bern_lp;
    out[1572864u + w]  = acc ? 1.0f : 0.0f;
}

extern "C" void kernel_launch(void* const* d_in, const int* in_sizes, int n_in,
                              void* d_out, int out_size) {
    const float* x = (const float*)d_in[0];
    float* out = (float*)d_out;
    keypoint_sampler_kernel<<<4096, 128>>>(x, out);
}